// round 3
// baseline (speedup 1.0000x reference)
#include <cuda_runtime.h>
#include <cstddef>

#define N_NODES_MAX 50000
#define N_EDGES_MAX 800000
#define IN_CH 128
#define HID 64

// ---------------- device scratch (no allocation allowed) ----------------
__device__ int   g_deg[N_NODES_MAX];
__device__ int   g_cursor[N_NODES_MAX];
__device__ int   g_row[N_NODES_MAX + 1];
__device__ float g_dinv[N_NODES_MAX];
__device__ int   g_col[N_EDGES_MAX];          // src node ids sorted by dst
__device__ float g_P[N_NODES_MAX * 64];       // projection buffer (reused both layers)
__device__ float g_H[N_NODES_MAX * 64];       // hidden activations after layer 1

// ---------------- CSR build ----------------
__global__ void zero_deg_kernel(int n) {
    int i = blockIdx.x * blockDim.x + threadIdx.x;
    if (i < n) g_deg[i] = 0;
}

__global__ void count_deg_kernel(const int* __restrict__ dst, int n_edges) {
    int i = blockIdx.x * blockDim.x + threadIdx.x;
    if (i < n_edges) atomicAdd(&g_deg[dst[i]], 1);
}

// Single-block exclusive scan over g_deg -> g_row/g_cursor, plus dinv = rsqrt(deg+1).
__global__ void scan_kernel(int n) {
    __shared__ int warp_sums[32];
    __shared__ int s_carry;
    int tid = threadIdx.x;
    int lane = tid & 31;
    int wid = tid >> 5;
    if (tid == 0) s_carry = 0;
    __syncthreads();

    for (int base = 0; base < n; base += 1024) {
        int i = base + tid;
        int v = (i < n) ? g_deg[i] : 0;

        // warp inclusive scan
        int x = v;
        #pragma unroll
        for (int off = 1; off < 32; off <<= 1) {
            int y = __shfl_up_sync(0xFFFFFFFFu, x, off);
            if (lane >= off) x += y;
        }
        if (lane == 31) warp_sums[wid] = x;
        __syncthreads();
        if (wid == 0) {
            int w = warp_sums[lane];
            #pragma unroll
            for (int off = 1; off < 32; off <<= 1) {
                int y = __shfl_up_sync(0xFFFFFFFFu, w, off);
                if (lane >= off) w += y;
            }
            warp_sums[lane] = w;
        }
        __syncthreads();

        int warp_excl = (wid > 0) ? warp_sums[wid - 1] : 0;
        int incl = x + warp_excl;
        int carry = s_carry;
        if (i < n) {
            int excl = carry + incl - v;
            g_row[i] = excl;
            g_cursor[i] = excl;
            g_dinv[i] = rsqrtf((float)v + 1.0f);  // deg includes self-loop
        }
        __syncthreads();
        if (tid == 1023) s_carry = carry + warp_sums[31];
        __syncthreads();
    }
    if (tid == 0) g_row[n] = s_carry;
}

__global__ void fill_edges_kernel(const int* __restrict__ src,
                                  const int* __restrict__ dst, int n_edges) {
    int i = blockIdx.x * blockDim.x + threadIdx.x;
    if (i < n_edges) {
        int d = dst[i];
        int p = atomicAdd(&g_cursor[d], 1);
        g_col[p] = src[i];
    }
}

// ---------------- dense GEMM: Y[n,64] = X[n,K] @ W[K,64] ----------------
// 64x64 output tile per block, 256 threads, K chunked by 32, float4 smem paths.
template <int K>
__global__ void __launch_bounds__(256) gemm64_kernel(const float* __restrict__ X,
                                                     const float* __restrict__ W,
                                                     float* __restrict__ Y, int n) {
    const int KC = 32;
    __shared__ float Xs[KC][68];  // [k][row], 68 pad keeps rows 16B-aligned (272B)
    __shared__ float Ws[KC][68];  // [k][col]

    int t = threadIdx.x;
    int row0 = blockIdx.x * 64;
    int ty = t >> 4;   // 0..15 -> 4 rows each
    int tx = t & 15;   // 0..15 -> 4 cols each

    float acc[4][4];
    #pragma unroll
    for (int i = 0; i < 4; i++)
        #pragma unroll
        for (int j = 0; j < 4; j++) acc[i][j] = 0.0f;

    for (int kc = 0; kc < K; kc += KC) {
        // load X chunk: 64 rows x 32 k = 512 float4 -> 2 per thread
        #pragma unroll
        for (int u = 0; u < 2; u++) {
            int idx = t + u * 256;
            int r = idx >> 3;        // 0..63
            int q = idx & 7;         // 0..7 (float4 along k)
            int row = row0 + r;
            if (row >= n) row = n - 1;
            float4 v = *reinterpret_cast<const float4*>(X + (size_t)row * K + kc + q * 4);
            Xs[q * 4 + 0][r] = v.x;
            Xs[q * 4 + 1][r] = v.y;
            Xs[q * 4 + 2][r] = v.z;
            Xs[q * 4 + 3][r] = v.w;
        }
        // load W chunk: 32 k x 64 col = 512 float4 -> 2 per thread
        #pragma unroll
        for (int u = 0; u < 2; u++) {
            int idx = t + u * 256;
            int kk = idx >> 4;       // 0..31
            int q = idx & 15;        // 0..15 (float4 along col)
            float4 v = *reinterpret_cast<const float4*>(W + (size_t)(kc + kk) * 64 + q * 4);
            *reinterpret_cast<float4*>(&Ws[kk][q * 4]) = v;
        }
        __syncthreads();

        #pragma unroll
        for (int kk = 0; kk < KC; kk++) {
            float4 a = *reinterpret_cast<const float4*>(&Xs[kk][ty * 4]);
            float4 b = *reinterpret_cast<const float4*>(&Ws[kk][tx * 4]);
            acc[0][0] += a.x * b.x; acc[0][1] += a.x * b.y; acc[0][2] += a.x * b.z; acc[0][3] += a.x * b.w;
            acc[1][0] += a.y * b.x; acc[1][1] += a.y * b.y; acc[1][2] += a.y * b.z; acc[1][3] += a.y * b.w;
            acc[2][0] += a.z * b.x; acc[2][1] += a.z * b.y; acc[2][2] += a.z * b.z; acc[2][3] += a.z * b.w;
            acc[3][0] += a.w * b.x; acc[3][1] += a.w * b.y; acc[3][2] += a.w * b.z; acc[3][3] += a.w * b.w;
        }
        __syncthreads();
    }

    #pragma unroll
    for (int i = 0; i < 4; i++) {
        int row = row0 + ty * 4 + i;
        if (row < n) {
            float4 o = make_float4(acc[i][0], acc[i][1], acc[i][2], acc[i][3]);
            *reinterpret_cast<float4*>(Y + (size_t)row * 64 + tx * 4) = o;
        }
    }
}

// ---------------- aggregation: warp per node, 64ch as float2/lane ----------------
template <bool RELU>
__global__ void __launch_bounds__(256) spmm64_kernel(const float* __restrict__ P,
                                                     const float* __restrict__ bias,
                                                     float* __restrict__ Y, int n) {
    int warp = (blockIdx.x * blockDim.x + threadIdx.x) >> 5;
    if (warp >= n) return;
    int lane = threadIdx.x & 31;

    const float2* Pv = reinterpret_cast<const float2*>(P);
    float di = g_dinv[warp];

    // self-loop contribution: dinv^2 * P[node]
    float2 acc = Pv[(size_t)warp * 32 + lane];
    float w0 = di * di;
    acc.x *= w0;
    acc.y *= w0;

    int e = g_row[warp];
    int end = g_row[warp + 1];
    // 2-way unrolled gather for MLP
    for (; e + 2 <= end; e += 2) {
        int s0 = g_col[e];
        int s1 = g_col[e + 1];
        float wa = di * g_dinv[s0];
        float wb = di * g_dinv[s1];
        float2 v0 = Pv[(size_t)s0 * 32 + lane];
        float2 v1 = Pv[(size_t)s1 * 32 + lane];
        acc.x += v0.x * wa; acc.y += v0.y * wa;
        acc.x += v1.x * wb; acc.y += v1.y * wb;
    }
    if (e < end) {
        int s0 = g_col[e];
        float wa = di * g_dinv[s0];
        float2 v0 = Pv[(size_t)s0 * 32 + lane];
        acc.x += v0.x * wa; acc.y += v0.y * wa;
    }

    float2 b = reinterpret_cast<const float2*>(bias)[lane];
    acc.x += b.x;
    acc.y += b.y;
    if (RELU) {
        acc.x = fmaxf(acc.x, 0.0f);
        acc.y = fmaxf(acc.y, 0.0f);
    }
    reinterpret_cast<float2*>(Y)[(size_t)warp * 32 + lane] = acc;
}

// ---------------- launcher ----------------
extern "C" void kernel_launch(void* const* d_in, const int* in_sizes, int n_in,
                              void* d_out, int out_size) {
    const float* x  = (const float*)d_in[0];       // [n, 128]
    const int*   ei = (const int*)d_in[1];         // [2, E]
    const float* W1 = (const float*)d_in[2];       // [128, 64]
    const float* b1 = (const float*)d_in[3];       // [64]
    const float* W2 = (const float*)d_in[4];       // [64, 64]
    const float* b2 = (const float*)d_in[5];       // [64]
    float* out = (float*)d_out;                    // [n, 64]

    int n = in_sizes[0] / IN_CH;
    int E = in_sizes[1] / 2;
    const int* src = ei;
    const int* dst = ei + E;

    void* p;
    cudaGetSymbolAddress(&p, g_P);
    float* P = (float*)p;
    cudaGetSymbolAddress(&p, g_H);
    float* H = (float*)p;

    // 1) build CSR-by-dst + symmetric norm
    zero_deg_kernel<<<(n + 255) / 256, 256>>>(n);
    count_deg_kernel<<<(E + 255) / 256, 256>>>(dst, E);
    scan_kernel<<<1, 1024>>>(n);
    fill_edges_kernel<<<(E + 255) / 256, 256>>>(src, dst, E);

    int spmm_blocks = (n * 32 + 255) / 256;
    int gemm_blocks = (n + 63) / 64;

    // 2) layer 1: project, aggregate, +b1, relu
    gemm64_kernel<IN_CH><<<gemm_blocks, 256>>>(x, W1, P, n);
    spmm64_kernel<true><<<spmm_blocks, 256>>>(P, b1, H, n);

    // 3) layer 2: project, aggregate, +b2
    gemm64_kernel<HID><<<gemm_blocks, 256>>>(H, W2, P, n);
    spmm64_kernel<false><<<spmm_blocks, 256>>>(P, b2, out, n);
}

// round 4
// speedup vs baseline: 1.3246x; 1.3246x over previous
#include <cuda_runtime.h>
#include <cstddef>

#define N_NODES_MAX 50000
#define N_EDGES_MAX 800000
#define IN_CH 128
#define HID 64
#define SCAN_B 1024

// ---------------- device scratch (no allocation allowed) ----------------
__device__ int   g_deg[N_NODES_MAX];
__device__ int   g_cursor[N_NODES_MAX];
__device__ int   g_row[N_NODES_MAX + 1];
__device__ float g_dinv[N_NODES_MAX];
__device__ int   g_col[N_EDGES_MAX];          // src ids grouped by dst
__device__ int   g_bsum[(N_NODES_MAX + SCAN_B - 1) / SCAN_B + 1];
__device__ int   g_boff[(N_NODES_MAX + SCAN_B - 1) / SCAN_B + 1];
__device__ float g_P[N_NODES_MAX * 64];       // projection buffer (both layers)
__device__ float g_H[N_NODES_MAX * 64];       // hidden activations

// ---------------- CSR build ----------------
__global__ void zero_deg_kernel(int n) {
    int i = blockIdx.x * blockDim.x + threadIdx.x;
    if (i < n) g_deg[i] = 0;
}

// 4 edges per thread for memory-level parallelism on the atomics
__global__ void count_deg_kernel(const int* __restrict__ dst, int n_edges) {
    int i0 = (blockIdx.x * blockDim.x + threadIdx.x) * 4;
    if (i0 + 3 < n_edges) {
        int d0 = dst[i0], d1 = dst[i0 + 1], d2 = dst[i0 + 2], d3 = dst[i0 + 3];
        atomicAdd(&g_deg[d0], 1);
        atomicAdd(&g_deg[d1], 1);
        atomicAdd(&g_deg[d2], 1);
        atomicAdd(&g_deg[d3], 1);
    } else {
        #pragma unroll
        for (int j = 0; j < 4; j++)
            if (i0 + j < n_edges) atomicAdd(&g_deg[dst[i0 + j]], 1);
    }
}

__device__ __forceinline__ int block_scan_incl(int v, int* warp_sums) {
    int lane = threadIdx.x & 31;
    int wid = threadIdx.x >> 5;
    int x = v;
    #pragma unroll
    for (int off = 1; off < 32; off <<= 1) {
        int y = __shfl_up_sync(0xFFFFFFFFu, x, off);
        if (lane >= off) x += y;
    }
    if (lane == 31) warp_sums[wid] = x;
    __syncthreads();
    if (wid == 0) {
        int w = warp_sums[lane];
        #pragma unroll
        for (int off = 1; off < 32; off <<= 1) {
            int y = __shfl_up_sync(0xFFFFFFFFu, w, off);
            if (lane >= off) w += y;
        }
        warp_sums[lane] = w;
    }
    __syncthreads();
    return x + ((wid > 0) ? warp_sums[wid - 1] : 0);
}

// pass 1: per-block local exclusive scan of degrees -> g_row, block total -> g_bsum
__global__ void __launch_bounds__(SCAN_B) scan_local_kernel(int n) {
    __shared__ int warp_sums[32];
    int i = blockIdx.x * SCAN_B + threadIdx.x;
    int v = (i < n) ? g_deg[i] : 0;
    int incl = block_scan_incl(v, warp_sums);
    if (i < n) {
        g_row[i] = incl - v;              // local exclusive
        g_dinv[i] = rsqrtf((float)v + 1.0f);  // deg incl. self-loop
    }
    if (threadIdx.x == 0) g_bsum[blockIdx.x] = warp_sums[31];
}

// pass 2: scan the (<=1024) block sums in a single block
__global__ void __launch_bounds__(SCAN_B) scan_bsum_kernel(int nb, int n) {
    __shared__ int warp_sums[32];
    int i = threadIdx.x;
    int v = (i < nb) ? g_bsum[i] : 0;
    int incl = block_scan_incl(v, warp_sums);
    if (i < nb) g_boff[i] = incl - v;
    if (i == 0) g_row[n] = warp_sums[31];  // total edge count
}

// pass 3: add block offsets, write cursor
__global__ void __launch_bounds__(SCAN_B) scan_add_kernel(int n) {
    int i = blockIdx.x * SCAN_B + threadIdx.x;
    if (i < n) {
        int r = g_row[i] + g_boff[blockIdx.x];
        g_row[i] = r;
        g_cursor[i] = r;
    }
}

__global__ void fill_edges_kernel(const int* __restrict__ src,
                                  const int* __restrict__ dst, int n_edges) {
    int i0 = (blockIdx.x * blockDim.x + threadIdx.x) * 4;
    if (i0 + 3 < n_edges) {
        int d0 = dst[i0], d1 = dst[i0 + 1], d2 = dst[i0 + 2], d3 = dst[i0 + 3];
        int s0 = src[i0], s1 = src[i0 + 1], s2 = src[i0 + 2], s3 = src[i0 + 3];
        int p0 = atomicAdd(&g_cursor[d0], 1);
        int p1 = atomicAdd(&g_cursor[d1], 1);
        int p2 = atomicAdd(&g_cursor[d2], 1);
        int p3 = atomicAdd(&g_cursor[d3], 1);
        g_col[p0] = s0; g_col[p1] = s1; g_col[p2] = s2; g_col[p3] = s3;
    } else {
        #pragma unroll
        for (int j = 0; j < 4; j++)
            if (i0 + j < n_edges) {
                int p = atomicAdd(&g_cursor[dst[i0 + j]], 1);
                g_col[p] = src[i0 + j];
            }
    }
}

// ---------------- dense GEMM: Y[n,64] = X[n,K] @ W[K,64] ----------------
// 128x64 tile per block, 128 threads, 8x8 microtile, K chunked by 32.
template <int K>
__global__ void __launch_bounds__(128) gemm128_kernel(const float* __restrict__ X,
                                                      const float* __restrict__ W,
                                                      float* __restrict__ Y, int n) {
    const int KC = 32;
    __shared__ float Xs[KC][132];  // [k][row]; 132*4=528B rows, 16B aligned
    __shared__ float Ws[KC][68];   // [k][col]; 272B rows, 16B aligned

    int t = threadIdx.x;
    int row0 = blockIdx.x * 128;
    int ty = t >> 3;   // 0..15 -> 8 rows each
    int tx = t & 7;    // 0..7  -> 8 cols each

    float acc[8][8];
    #pragma unroll
    for (int i = 0; i < 8; i++)
        #pragma unroll
        for (int j = 0; j < 8; j++) acc[i][j] = 0.0f;

    for (int kc = 0; kc < K; kc += KC) {
        // X chunk: 128 rows x 32 k = 1024 float4 -> 8 per thread (coalesced)
        #pragma unroll
        for (int u = 0; u < 8; u++) {
            int idx = t + u * 128;
            int r = idx >> 3;        // 0..127
            int q = idx & 7;         // float4 along k
            int row = row0 + r;
            if (row >= n) row = n - 1;
            float4 v = *reinterpret_cast<const float4*>(X + (size_t)row * K + kc + q * 4);
            Xs[q * 4 + 0][r] = v.x;
            Xs[q * 4 + 1][r] = v.y;
            Xs[q * 4 + 2][r] = v.z;
            Xs[q * 4 + 3][r] = v.w;
        }
        // W chunk: 32 k x 64 col = 512 float4 -> 4 per thread
        #pragma unroll
        for (int u = 0; u < 4; u++) {
            int idx = t + u * 128;
            int kk = idx >> 4;       // 0..31
            int q = idx & 15;        // float4 along col
            float4 v = *reinterpret_cast<const float4*>(W + (size_t)(kc + kk) * 64 + q * 4);
            *reinterpret_cast<float4*>(&Ws[kk][q * 4]) = v;
        }
        __syncthreads();

        #pragma unroll 8
        for (int kk = 0; kk < KC; kk++) {
            float a[8], b[8];
            *reinterpret_cast<float4*>(a)     = *reinterpret_cast<const float4*>(&Xs[kk][ty * 8]);
            *reinterpret_cast<float4*>(a + 4) = *reinterpret_cast<const float4*>(&Xs[kk][ty * 8 + 4]);
            *reinterpret_cast<float4*>(b)     = *reinterpret_cast<const float4*>(&Ws[kk][tx * 8]);
            *reinterpret_cast<float4*>(b + 4) = *reinterpret_cast<const float4*>(&Ws[kk][tx * 8 + 4]);
            #pragma unroll
            for (int i = 0; i < 8; i++)
                #pragma unroll
                for (int j = 0; j < 8; j++)
                    acc[i][j] += a[i] * b[j];
        }
        __syncthreads();
    }

    #pragma unroll
    for (int i = 0; i < 8; i++) {
        int row = row0 + ty * 8 + i;
        if (row < n) {
            float4 o0 = make_float4(acc[i][0], acc[i][1], acc[i][2], acc[i][3]);
            float4 o1 = make_float4(acc[i][4], acc[i][5], acc[i][6], acc[i][7]);
            *reinterpret_cast<float4*>(Y + (size_t)row * 64 + tx * 8)     = o0;
            *reinterpret_cast<float4*>(Y + (size_t)row * 64 + tx * 8 + 4) = o1;
        }
    }
}

// ---------------- aggregation: 16 lanes per node, float4/lane ----------------
template <bool RELU>
__global__ void __launch_bounds__(256) spmm64_kernel(const float* __restrict__ P,
                                                     const float* __restrict__ bias,
                                                     float* __restrict__ Y, int n) {
    int t = blockIdx.x * blockDim.x + threadIdx.x;
    int node = t >> 4;
    if (node >= n) return;
    int l = t & 15;

    const float4* Pv = reinterpret_cast<const float4*>(P);
    float di = g_dinv[node];

    // self-loop: dinv^2 * P[node]
    float4 acc = Pv[(size_t)node * 16 + l];
    float w0 = di * di;
    acc.x *= w0; acc.y *= w0; acc.z *= w0; acc.w *= w0;

    int e = g_row[node];
    int end = g_row[node + 1];
    for (; e + 2 <= end; e += 2) {
        int s0 = g_col[e];
        int s1 = g_col[e + 1];
        float wa = di * g_dinv[s0];
        float wb = di * g_dinv[s1];
        float4 v0 = Pv[(size_t)s0 * 16 + l];
        float4 v1 = Pv[(size_t)s1 * 16 + l];
        acc.x += v0.x * wa; acc.y += v0.y * wa; acc.z += v0.z * wa; acc.w += v0.w * wa;
        acc.x += v1.x * wb; acc.y += v1.y * wb; acc.z += v1.z * wb; acc.w += v1.w * wb;
    }
    if (e < end) {
        int s0 = g_col[e];
        float wa = di * g_dinv[s0];
        float4 v0 = Pv[(size_t)s0 * 16 + l];
        acc.x += v0.x * wa; acc.y += v0.y * wa; acc.z += v0.z * wa; acc.w += v0.w * wa;
    }

    float4 b = reinterpret_cast<const float4*>(bias)[l];
    acc.x += b.x; acc.y += b.y; acc.z += b.z; acc.w += b.w;
    if (RELU) {
        acc.x = fmaxf(acc.x, 0.0f);
        acc.y = fmaxf(acc.y, 0.0f);
        acc.z = fmaxf(acc.z, 0.0f);
        acc.w = fmaxf(acc.w, 0.0f);
    }
    reinterpret_cast<float4*>(Y)[(size_t)node * 16 + l] = acc;
}

// ---------------- launcher ----------------
extern "C" void kernel_launch(void* const* d_in, const int* in_sizes, int n_in,
                              void* d_out, int out_size) {
    const float* x  = (const float*)d_in[0];       // [n, 128]
    const int*   ei = (const int*)d_in[1];         // [2, E]
    const float* W1 = (const float*)d_in[2];       // [128, 64]
    const float* b1 = (const float*)d_in[3];       // [64]
    const float* W2 = (const float*)d_in[4];       // [64, 64]
    const float* b2 = (const float*)d_in[5];       // [64]
    float* out = (float*)d_out;                    // [n, 64]

    int n = in_sizes[0] / IN_CH;
    int E = in_sizes[1] / 2;
    const int* src = ei;
    const int* dst = ei + E;

    void* p;
    cudaGetSymbolAddress(&p, g_P);
    float* P = (float*)p;
    cudaGetSymbolAddress(&p, g_H);
    float* H = (float*)p;

    int nb = (n + SCAN_B - 1) / SCAN_B;
    int eb4 = (E + 4 * 256 - 1) / (4 * 256);

    // 1) build CSR-by-dst + symmetric norm
    zero_deg_kernel<<<(n + 255) / 256, 256>>>(n);
    count_deg_kernel<<<eb4, 256>>>(dst, E);
    scan_local_kernel<<<nb, SCAN_B>>>(n);
    scan_bsum_kernel<<<1, SCAN_B>>>(nb, n);
    scan_add_kernel<<<nb, SCAN_B>>>(n);
    fill_edges_kernel<<<eb4, 256>>>(src, dst, E);

    int spmm_blocks = (n * 16 + 255) / 256;
    int gemm_blocks = (n + 127) / 128;

    // 2) layer 1: project, aggregate, +b1, relu
    gemm128_kernel<IN_CH><<<gemm_blocks, 128>>>(x, W1, P, n);
    spmm64_kernel<true><<<spmm_blocks, 256>>>(P, b1, H, n);

    // 3) layer 2: project, aggregate, +b2
    gemm128_kernel<HID><<<gemm_blocks, 128>>>(H, W2, P, n);
    spmm64_kernel<false><<<spmm_blocks, 256>>>(P, b2, out, n);
}

// round 5
// speedup vs baseline: 1.4548x; 1.0983x over previous
#include <cuda_runtime.h>
#include <cuda_fp16.h>
#include <cstddef>

#define N_NODES_MAX 50000
#define N_EDGES_MAX 800000
#define IN_CH 128
#define HID 64
#define SCAN_B 1024

// ---------------- device scratch (no allocation allowed) ----------------
__device__ int    g_deg[N_NODES_MAX];
__device__ int    g_cursor[N_NODES_MAX];
__device__ int    g_row[N_NODES_MAX + 1];
__device__ float  g_dinv[N_NODES_MAX];
__device__ int    g_col[N_EDGES_MAX];          // src ids grouped by dst
__device__ int    g_bsum[(N_NODES_MAX + SCAN_B - 1) / SCAN_B + 1];
__device__ __half g_P[N_NODES_MAX * 64];       // fp16 projection buffer (both layers)
__device__ float  g_H[N_NODES_MAX * 64];       // fp32 hidden activations

// ---------------- CSR build ----------------
__global__ void zero_deg_kernel(int n) {
    int i = blockIdx.x * blockDim.x + threadIdx.x;
    if (i < n) g_deg[i] = 0;
}

// 8 edges per thread: keep many independent atomics in flight (ATOMG latency-bound)
__global__ void count_deg_kernel(const int* __restrict__ dst, int n_edges) {
    int i0 = (blockIdx.x * blockDim.x + threadIdx.x) * 8;
    if (i0 + 8 <= n_edges) {
        int d[8];
        #pragma unroll
        for (int j = 0; j < 8; j++) d[j] = dst[i0 + j];
        #pragma unroll
        for (int j = 0; j < 8; j++) atomicAdd(&g_deg[d[j]], 1);
    } else {
        for (int j = 0; j < 8 && i0 + j < n_edges; j++)
            atomicAdd(&g_deg[dst[i0 + j]], 1);
    }
}

__device__ __forceinline__ int block_scan_incl(int v, int* warp_sums) {
    int lane = threadIdx.x & 31;
    int wid = threadIdx.x >> 5;
    int x = v;
    #pragma unroll
    for (int off = 1; off < 32; off <<= 1) {
        int y = __shfl_up_sync(0xFFFFFFFFu, x, off);
        if (lane >= off) x += y;
    }
    if (lane == 31) warp_sums[wid] = x;
    __syncthreads();
    if (wid == 0) {
        int w = warp_sums[lane];
        #pragma unroll
        for (int off = 1; off < 32; off <<= 1) {
            int y = __shfl_up_sync(0xFFFFFFFFu, w, off);
            if (lane >= off) w += y;
        }
        warp_sums[lane] = w;
    }
    __syncthreads();
    return x + ((wid > 0) ? warp_sums[wid - 1] : 0);
}

// pass 1: per-block local exclusive scan of degrees -> g_row, block total -> g_bsum
__global__ void __launch_bounds__(SCAN_B) scan_local_kernel(int n) {
    __shared__ int warp_sums[32];
    int i = blockIdx.x * SCAN_B + threadIdx.x;
    int v = (i < n) ? g_deg[i] : 0;
    int incl = block_scan_incl(v, warp_sums);
    if (i < n) {
        g_row[i] = incl - v;                  // local exclusive
        g_dinv[i] = rsqrtf((float)v + 1.0f);  // deg incl. self-loop
    }
    if (threadIdx.x == 0) g_bsum[blockIdx.x] = warp_sums[31];
}

// pass 2 (fused): each block reduces bsum[0..blockIdx.x) itself (nb <= 49)
__global__ void __launch_bounds__(SCAN_B) scan_add_kernel(int n, int E) {
    __shared__ int s_off;
    if (threadIdx.x < 32) {
        int s = 0;
        for (int j = threadIdx.x; j < (int)blockIdx.x; j += 32) s += g_bsum[j];
        #pragma unroll
        for (int o = 16; o; o >>= 1) s += __shfl_down_sync(0xFFFFFFFFu, s, o);
        if (threadIdx.x == 0) s_off = s;
    }
    __syncthreads();
    int i = blockIdx.x * SCAN_B + threadIdx.x;
    if (i < n) {
        int r = g_row[i] + s_off;
        g_row[i] = r;
        g_cursor[i] = r;
    }
    if (blockIdx.x == 0 && threadIdx.x == 0) g_row[n] = E;  // every edge is counted
}

__global__ void fill_edges_kernel(const int* __restrict__ src,
                                  const int* __restrict__ dst, int n_edges) {
    int i0 = (blockIdx.x * blockDim.x + threadIdx.x) * 8;
    if (i0 + 8 <= n_edges) {
        int d[8], s[8], p[8];
        #pragma unroll
        for (int j = 0; j < 8; j++) d[j] = dst[i0 + j];
        #pragma unroll
        for (int j = 0; j < 8; j++) s[j] = src[i0 + j];
        #pragma unroll
        for (int j = 0; j < 8; j++) p[j] = atomicAdd(&g_cursor[d[j]], 1);
        #pragma unroll
        for (int j = 0; j < 8; j++) g_col[p[j]] = s[j];
    } else {
        for (int j = 0; j < 8 && i0 + j < n_edges; j++) {
            int p = atomicAdd(&g_cursor[dst[i0 + j]], 1);
            g_col[p] = src[i0 + j];
        }
    }
}

// ---------------- dense GEMM: Y[n,64](fp16) = X[n,K](fp32) @ W[K,64] ----------------
// 128x64 tile per block, 128 threads, 8x8 microtile, K chunked by 32.
template <int K>
__global__ void __launch_bounds__(128) gemm128_kernel(const float* __restrict__ X,
                                                      const float* __restrict__ W,
                                                      __half* __restrict__ Y, int n) {
    const int KC = 32;
    __shared__ float Xs[KC][132];
    __shared__ float Ws[KC][68];

    int t = threadIdx.x;
    int row0 = blockIdx.x * 128;
    int ty = t >> 3;   // 0..15 -> 8 rows each
    int tx = t & 7;    // 0..7  -> 8 cols each

    float acc[8][8];
    #pragma unroll
    for (int i = 0; i < 8; i++)
        #pragma unroll
        for (int j = 0; j < 8; j++) acc[i][j] = 0.0f;

    for (int kc = 0; kc < K; kc += KC) {
        #pragma unroll
        for (int u = 0; u < 8; u++) {
            int idx = t + u * 128;
            int r = idx >> 3;
            int q = idx & 7;
            int row = row0 + r;
            if (row >= n) row = n - 1;
            float4 v = *reinterpret_cast<const float4*>(X + (size_t)row * K + kc + q * 4);
            Xs[q * 4 + 0][r] = v.x;
            Xs[q * 4 + 1][r] = v.y;
            Xs[q * 4 + 2][r] = v.z;
            Xs[q * 4 + 3][r] = v.w;
        }
        #pragma unroll
        for (int u = 0; u < 4; u++) {
            int idx = t + u * 128;
            int kk = idx >> 4;
            int q = idx & 15;
            float4 v = *reinterpret_cast<const float4*>(W + (size_t)(kc + kk) * 64 + q * 4);
            *reinterpret_cast<float4*>(&Ws[kk][q * 4]) = v;
        }
        __syncthreads();

        #pragma unroll 8
        for (int kk = 0; kk < KC; kk++) {
            float a[8], b[8];
            *reinterpret_cast<float4*>(a)     = *reinterpret_cast<const float4*>(&Xs[kk][ty * 8]);
            *reinterpret_cast<float4*>(a + 4) = *reinterpret_cast<const float4*>(&Xs[kk][ty * 8 + 4]);
            *reinterpret_cast<float4*>(b)     = *reinterpret_cast<const float4*>(&Ws[kk][tx * 8]);
            *reinterpret_cast<float4*>(b + 4) = *reinterpret_cast<const float4*>(&Ws[kk][tx * 8 + 4]);
            #pragma unroll
            for (int i = 0; i < 8; i++)
                #pragma unroll
                for (int j = 0; j < 8; j++)
                    acc[i][j] += a[i] * b[j];
        }
        __syncthreads();
    }

    #pragma unroll
    for (int i = 0; i < 8; i++) {
        int row = row0 + ty * 8 + i;
        if (row < n) {
            __half2 h[4];
            #pragma unroll
            for (int j = 0; j < 4; j++)
                h[j] = __floats2half2_rn(acc[i][2 * j], acc[i][2 * j + 1]);
            // 8 halves = 16 B, (row*64 + tx*8)*2 bytes is 16B-aligned
            *reinterpret_cast<uint4*>(Y + (size_t)row * 64 + tx * 8) =
                *reinterpret_cast<const uint4*>(h);
        }
    }
}

// ---------------- aggregation: 8 lanes/node, 16B (8 halves) per lane ----------------
// One edge gather = 8 lanes x 16B = exactly one 128B L2 line (P rows are 128B aligned).
template <bool RELU>
__global__ void __launch_bounds__(256) spmm64_kernel(const __half* __restrict__ P,
                                                     const float* __restrict__ bias,
                                                     float* __restrict__ Y, int n) {
    int t = blockIdx.x * blockDim.x + threadIdx.x;
    int node = t >> 3;
    if (node >= n) return;
    int l = t & 7;

    const uint4* Pv = reinterpret_cast<const uint4*>(P);  // 8 halves per uint4
    float di = g_dinv[node];
    float w0 = di * di;

    float acc[8];
    {
        uint4 v = Pv[(size_t)node * 8 + l];
        const __half2* hp = reinterpret_cast<const __half2*>(&v);
        #pragma unroll
        for (int j = 0; j < 4; j++) {
            float2 f = __half22float2(hp[j]);
            acc[2 * j]     = f.x * w0;
            acc[2 * j + 1] = f.y * w0;
        }
    }

    int e = g_row[node];
    int end = g_row[node + 1];
    for (; e + 2 <= end; e += 2) {
        int s0 = g_col[e];
        int s1 = g_col[e + 1];
        float wa = di * g_dinv[s0];
        float wb = di * g_dinv[s1];
        uint4 v0 = Pv[(size_t)s0 * 8 + l];
        uint4 v1 = Pv[(size_t)s1 * 8 + l];
        const __half2* h0 = reinterpret_cast<const __half2*>(&v0);
        const __half2* h1 = reinterpret_cast<const __half2*>(&v1);
        #pragma unroll
        for (int j = 0; j < 4; j++) {
            float2 f0 = __half22float2(h0[j]);
            float2 f1 = __half22float2(h1[j]);
            acc[2 * j]     += f0.x * wa + f1.x * wb;
            acc[2 * j + 1] += f0.y * wa + f1.y * wb;
        }
    }
    if (e < end) {
        int s0 = g_col[e];
        float wa = di * g_dinv[s0];
        uint4 v0 = Pv[(size_t)s0 * 8 + l];
        const __half2* h0 = reinterpret_cast<const __half2*>(&v0);
        #pragma unroll
        for (int j = 0; j < 4; j++) {
            float2 f0 = __half22float2(h0[j]);
            acc[2 * j]     += f0.x * wa;
            acc[2 * j + 1] += f0.y * wa;
        }
    }

    float4 b0 = reinterpret_cast<const float4*>(bias)[l * 2];
    float4 b1 = reinterpret_cast<const float4*>(bias)[l * 2 + 1];
    acc[0] += b0.x; acc[1] += b0.y; acc[2] += b0.z; acc[3] += b0.w;
    acc[4] += b1.x; acc[5] += b1.y; acc[6] += b1.z; acc[7] += b1.w;
    if (RELU) {
        #pragma unroll
        for (int j = 0; j < 8; j++) acc[j] = fmaxf(acc[j], 0.0f);
    }
    float4* Yo = reinterpret_cast<float4*>(Y + (size_t)node * 64 + l * 8);
    Yo[0] = make_float4(acc[0], acc[1], acc[2], acc[3]);
    Yo[1] = make_float4(acc[4], acc[5], acc[6], acc[7]);
}

// ---------------- launcher ----------------
extern "C" void kernel_launch(void* const* d_in, const int* in_sizes, int n_in,
                              void* d_out, int out_size) {
    const float* x  = (const float*)d_in[0];       // [n, 128]
    const int*   ei = (const int*)d_in[1];         // [2, E]
    const float* W1 = (const float*)d_in[2];       // [128, 64]
    const float* b1 = (const float*)d_in[3];       // [64]
    const float* W2 = (const float*)d_in[4];       // [64, 64]
    const float* b2 = (const float*)d_in[5];       // [64]
    float* out = (float*)d_out;                    // [n, 64]

    int n = in_sizes[0] / IN_CH;
    int E = in_sizes[1] / 2;
    const int* src = ei;
    const int* dst = ei + E;

    void* p;
    cudaGetSymbolAddress(&p, g_P);
    __half* P = (__half*)p;
    cudaGetSymbolAddress(&p, g_H);
    float* H = (float*)p;

    int nb = (n + SCAN_B - 1) / SCAN_B;
    int eb8 = (E + 8 * 256 - 1) / (8 * 256);

    // 1) build CSR-by-dst + symmetric norm (5 launches)
    zero_deg_kernel<<<(n + 255) / 256, 256>>>(n);
    count_deg_kernel<<<eb8, 256>>>(dst, E);
    scan_local_kernel<<<nb, SCAN_B>>>(n);
    scan_add_kernel<<<nb, SCAN_B>>>(n, E);
    fill_edges_kernel<<<eb8, 256>>>(src, dst, E);

    int spmm_blocks = (n * 8 + 255) / 256;
    int gemm_blocks = (n + 127) / 128;

    // 2) layer 1: project (fp16 out), aggregate, +b1, relu
    gemm128_kernel<IN_CH><<<gemm_blocks, 128>>>(x, W1, P, n);
    spmm64_kernel<true><<<spmm_blocks, 256>>>(P, b1, H, n);

    // 3) layer 2: project, aggregate, +b2
    gemm128_kernel<HID><<<gemm_blocks, 128>>>(H, W2, P, n);
    spmm64_kernel<false><<<spmm_blocks, 256>>>(P, b2, out, n);
}

// round 6
// speedup vs baseline: 1.6796x; 1.1545x over previous
#include <cuda_runtime.h>
#include <cuda_fp16.h>
#include <cstddef>

#define N_NODES_MAX 50000
#define N_EDGES_MAX 800000
#define IN_CH 128
#define HID 64
#define SCAN_B 1024

// ---------------- device scratch (no allocation allowed) ----------------
__device__ int    g_deg[N_NODES_MAX];
__device__ int    g_cursor[N_NODES_MAX];
__device__ int    g_row[N_NODES_MAX + 1];
__device__ float  g_dinv[N_NODES_MAX];
__device__ int    g_col[N_EDGES_MAX];          // src ids grouped by dst
__device__ int    g_bsum[(N_NODES_MAX + SCAN_B - 1) / SCAN_B + 1];
__device__ int    g_ready;                     // lookback counter (zeroed by count kernel)
__device__ __half g_P[N_NODES_MAX * 64];       // fp16 projection buffer (both layers)
__device__ float  g_H[N_NODES_MAX * 64];       // fp32 hidden activations

// ---------------- CSR build ----------------
__global__ void zero_deg_kernel(int n) {
    int i = blockIdx.x * blockDim.x + threadIdx.x;
    if (i < n) g_deg[i] = 0;
}

// 8 edges per thread (2x int4 loads): many independent atomics in flight
__global__ void count_deg_kernel(const int* __restrict__ dst, int n_edges) {
    if (blockIdx.x == 0 && threadIdx.x == 0) g_ready = 0;  // for scan_fused (runs after, same stream)
    int i0 = (blockIdx.x * blockDim.x + threadIdx.x) * 8;
    if (i0 + 8 <= n_edges) {
        int4 a = *reinterpret_cast<const int4*>(dst + i0);
        int4 b = *reinterpret_cast<const int4*>(dst + i0 + 4);
        atomicAdd(&g_deg[a.x], 1); atomicAdd(&g_deg[a.y], 1);
        atomicAdd(&g_deg[a.z], 1); atomicAdd(&g_deg[a.w], 1);
        atomicAdd(&g_deg[b.x], 1); atomicAdd(&g_deg[b.y], 1);
        atomicAdd(&g_deg[b.z], 1); atomicAdd(&g_deg[b.w], 1);
    } else {
        for (int j = 0; j < 8 && i0 + j < n_edges; j++)
            atomicAdd(&g_deg[dst[i0 + j]], 1);
    }
}

__device__ __forceinline__ int block_scan_incl(int v, int* warp_sums) {
    int lane = threadIdx.x & 31;
    int wid = threadIdx.x >> 5;
    int x = v;
    #pragma unroll
    for (int off = 1; off < 32; off <<= 1) {
        int y = __shfl_up_sync(0xFFFFFFFFu, x, off);
        if (lane >= off) x += y;
    }
    if (lane == 31) warp_sums[wid] = x;
    __syncthreads();
    if (wid == 0) {
        int w = warp_sums[lane];
        #pragma unroll
        for (int off = 1; off < 32; off <<= 1) {
            int y = __shfl_up_sync(0xFFFFFFFFu, w, off);
            if (lane >= off) w += y;
        }
        warp_sums[lane] = w;
    }
    __syncthreads();
    return x + ((wid > 0) ? warp_sums[wid - 1] : 0);
}

// Single-pass scan: local scan, publish block sum, grid-resident wait (49 blocks
// all co-resident on 148 SMs -> spin is deadlock-free), then add prefix offset.
__global__ void __launch_bounds__(SCAN_B) scan_fused_kernel(int n, int E) {
    __shared__ int warp_sums[32];
    __shared__ int s_off;
    int b = blockIdx.x;
    int i = b * SCAN_B + threadIdx.x;
    int v = (i < n) ? g_deg[i] : 0;
    int incl = block_scan_incl(v, warp_sums);

    if (threadIdx.x == 0) {
        g_bsum[b] = warp_sums[31];
        __threadfence();
        atomicAdd(&g_ready, 1);
        while (atomicAdd(&g_ready, 0) < (int)gridDim.x) {}
        __threadfence();
        int s = 0;
        for (int j = 0; j < b; j++) s += g_bsum[j];
        s_off = s;
    }
    __syncthreads();

    if (i < n) {
        int r = incl - v + s_off;
        g_row[i] = r;
        g_cursor[i] = r;
        g_dinv[i] = rsqrtf((float)v + 1.0f);  // deg incl. self-loop
    }
    if (b == 0 && threadIdx.x == 0) g_row[n] = E;
}

__global__ void fill_edges_kernel(const int* __restrict__ src,
                                  const int* __restrict__ dst, int n_edges) {
    int i0 = (blockIdx.x * blockDim.x + threadIdx.x) * 8;
    if (i0 + 8 <= n_edges) {
        int4 da = *reinterpret_cast<const int4*>(dst + i0);
        int4 db = *reinterpret_cast<const int4*>(dst + i0 + 4);
        int4 sa = *reinterpret_cast<const int4*>(src + i0);
        int4 sb = *reinterpret_cast<const int4*>(src + i0 + 4);
        int p0 = atomicAdd(&g_cursor[da.x], 1);
        int p1 = atomicAdd(&g_cursor[da.y], 1);
        int p2 = atomicAdd(&g_cursor[da.z], 1);
        int p3 = atomicAdd(&g_cursor[da.w], 1);
        int p4 = atomicAdd(&g_cursor[db.x], 1);
        int p5 = atomicAdd(&g_cursor[db.y], 1);
        int p6 = atomicAdd(&g_cursor[db.z], 1);
        int p7 = atomicAdd(&g_cursor[db.w], 1);
        g_col[p0] = sa.x; g_col[p1] = sa.y; g_col[p2] = sa.z; g_col[p3] = sa.w;
        g_col[p4] = sb.x; g_col[p5] = sb.y; g_col[p6] = sb.z; g_col[p7] = sb.w;
    } else {
        for (int j = 0; j < 8 && i0 + j < n_edges; j++) {
            int p = atomicAdd(&g_cursor[dst[i0 + j]], 1);
            g_col[p] = src[i0 + j];
        }
    }
}

// ---------------- dense GEMM: Y[n,64](fp16) = X[n,K](fp32) @ W[K,64] ----------------
template <int K>
__global__ void __launch_bounds__(128) gemm128_kernel(const float* __restrict__ X,
                                                      const float* __restrict__ W,
                                                      __half* __restrict__ Y, int n) {
    const int KC = 32;
    __shared__ float Xs[KC][132];
    __shared__ float Ws[KC][68];

    int t = threadIdx.x;
    int row0 = blockIdx.x * 128;
    int ty = t >> 3;   // 0..15 -> 8 rows each
    int tx = t & 7;    // 0..7  -> 8 cols each

    float acc[8][8];
    #pragma unroll
    for (int i = 0; i < 8; i++)
        #pragma unroll
        for (int j = 0; j < 8; j++) acc[i][j] = 0.0f;

    for (int kc = 0; kc < K; kc += KC) {
        #pragma unroll
        for (int u = 0; u < 8; u++) {
            int idx = t + u * 128;
            int r = idx >> 3;
            int q = idx & 7;
            int row = row0 + r;
            if (row >= n) row = n - 1;
            float4 v = *reinterpret_cast<const float4*>(X + (size_t)row * K + kc + q * 4);
            Xs[q * 4 + 0][r] = v.x;
            Xs[q * 4 + 1][r] = v.y;
            Xs[q * 4 + 2][r] = v.z;
            Xs[q * 4 + 3][r] = v.w;
        }
        #pragma unroll
        for (int u = 0; u < 4; u++) {
            int idx = t + u * 128;
            int kk = idx >> 4;
            int q = idx & 15;
            float4 v = *reinterpret_cast<const float4*>(W + (size_t)(kc + kk) * 64 + q * 4);
            *reinterpret_cast<float4*>(&Ws[kk][q * 4]) = v;
        }
        __syncthreads();

        #pragma unroll 8
        for (int kk = 0; kk < KC; kk++) {
            float a[8], b[8];
            *reinterpret_cast<float4*>(a)     = *reinterpret_cast<const float4*>(&Xs[kk][ty * 8]);
            *reinterpret_cast<float4*>(a + 4) = *reinterpret_cast<const float4*>(&Xs[kk][ty * 8 + 4]);
            *reinterpret_cast<float4*>(b)     = *reinterpret_cast<const float4*>(&Ws[kk][tx * 8]);
            *reinterpret_cast<float4*>(b + 4) = *reinterpret_cast<const float4*>(&Ws[kk][tx * 8 + 4]);
            #pragma unroll
            for (int i = 0; i < 8; i++)
                #pragma unroll
                for (int j = 0; j < 8; j++)
                    acc[i][j] += a[i] * b[j];
        }
        __syncthreads();
    }

    #pragma unroll
    for (int i = 0; i < 8; i++) {
        int row = row0 + ty * 8 + i;
        if (row < n) {
            __half2 h[4];
            #pragma unroll
            for (int j = 0; j < 4; j++)
                h[j] = __floats2half2_rn(acc[i][2 * j], acc[i][2 * j + 1]);
            *reinterpret_cast<uint4*>(Y + (size_t)row * 64 + tx * 8) =
                *reinterpret_cast<const uint4*>(h);
        }
    }
}

// ---------------- aggregation: 8 lanes/node, 16B (8 halves) per lane ----------------
template <bool RELU>
__global__ void __launch_bounds__(256) spmm64_kernel(const __half* __restrict__ P,
                                                     const float* __restrict__ bias,
                                                     float* __restrict__ Y, int n) {
    int t = blockIdx.x * blockDim.x + threadIdx.x;
    int node = t >> 3;
    if (node >= n) return;
    int l = t & 7;

    const uint4* Pv = reinterpret_cast<const uint4*>(P);
    float di = g_dinv[node];
    float w0 = di * di;

    float acc[8];
    {
        uint4 v = Pv[(size_t)node * 8 + l];
        const __half2* hp = reinterpret_cast<const __half2*>(&v);
        #pragma unroll
        for (int j = 0; j < 4; j++) {
            float2 f = __half22float2(hp[j]);
            acc[2 * j]     = f.x * w0;
            acc[2 * j + 1] = f.y * w0;
        }
    }

    int e = g_row[node];
    int end = g_row[node + 1];
    // 4-way unrolled gathers: 4 independent 128B-line loads in flight
    for (; e + 4 <= end; e += 4) {
        int s0 = g_col[e], s1 = g_col[e + 1], s2 = g_col[e + 2], s3 = g_col[e + 3];
        float wa = di * g_dinv[s0];
        float wb = di * g_dinv[s1];
        float wc = di * g_dinv[s2];
        float wd = di * g_dinv[s3];
        uint4 v0 = Pv[(size_t)s0 * 8 + l];
        uint4 v1 = Pv[(size_t)s1 * 8 + l];
        uint4 v2 = Pv[(size_t)s2 * 8 + l];
        uint4 v3 = Pv[(size_t)s3 * 8 + l];
        const __half2* h0 = reinterpret_cast<const __half2*>(&v0);
        const __half2* h1 = reinterpret_cast<const __half2*>(&v1);
        const __half2* h2 = reinterpret_cast<const __half2*>(&v2);
        const __half2* h3 = reinterpret_cast<const __half2*>(&v3);
        #pragma unroll
        for (int j = 0; j < 4; j++) {
            float2 f0 = __half22float2(h0[j]);
            float2 f1 = __half22float2(h1[j]);
            float2 f2 = __half22float2(h2[j]);
            float2 f3 = __half22float2(h3[j]);
            acc[2 * j]     += f0.x * wa + f1.x * wb + f2.x * wc + f3.x * wd;
            acc[2 * j + 1] += f0.y * wa + f1.y * wb + f2.y * wc + f3.y * wd;
        }
    }
    for (; e < end; e++) {
        int s0 = g_col[e];
        float wa = di * g_dinv[s0];
        uint4 v0 = Pv[(size_t)s0 * 8 + l];
        const __half2* h0 = reinterpret_cast<const __half2*>(&v0);
        #pragma unroll
        for (int j = 0; j < 4; j++) {
            float2 f0 = __half22float2(h0[j]);
            acc[2 * j]     += f0.x * wa;
            acc[2 * j + 1] += f0.y * wa;
        }
    }

    float4 b0 = reinterpret_cast<const float4*>(bias)[l * 2];
    float4 b1 = reinterpret_cast<const float4*>(bias)[l * 2 + 1];
    acc[0] += b0.x; acc[1] += b0.y; acc[2] += b0.z; acc[3] += b0.w;
    acc[4] += b1.x; acc[5] += b1.y; acc[6] += b1.z; acc[7] += b1.w;
    if (RELU) {
        #pragma unroll
        for (int j = 0; j < 8; j++) acc[j] = fmaxf(acc[j], 0.0f);
    }
    float4* Yo = reinterpret_cast<float4*>(Y + (size_t)node * 64 + l * 8);
    Yo[0] = make_float4(acc[0], acc[1], acc[2], acc[3]);
    Yo[1] = make_float4(acc[4], acc[5], acc[6], acc[7]);
}

// ---------------- launcher ----------------
extern "C" void kernel_launch(void* const* d_in, const int* in_sizes, int n_in,
                              void* d_out, int out_size) {
    const float* x  = (const float*)d_in[0];       // [n, 128]
    const int*   ei = (const int*)d_in[1];         // [2, E]
    const float* W1 = (const float*)d_in[2];       // [128, 64]
    const float* b1 = (const float*)d_in[3];       // [64]
    const float* W2 = (const float*)d_in[4];       // [64, 64]
    const float* b2 = (const float*)d_in[5];       // [64]
    float* out = (float*)d_out;                    // [n, 64]

    int n = in_sizes[0] / IN_CH;
    int E = in_sizes[1] / 2;
    const int* src = ei;
    const int* dst = ei + E;

    void* p;
    cudaGetSymbolAddress(&p, g_P);
    __half* P = (__half*)p;
    cudaGetSymbolAddress(&p, g_H);
    float* H = (float*)p;

    int nb = (n + SCAN_B - 1) / SCAN_B;
    int eb8 = (E + 8 * 256 - 1) / (8 * 256);
    int spmm_blocks = (n * 8 + 255) / 256;
    int gemm_blocks = (n + 127) / 128;

    // Fork a side stream so the CSR build overlaps GEMM1 (both independent).
    // Host-side objects only (no device allocation); not destroyed because
    // destroying capture-participating streams/events mid-capture is illegal.
    cudaStream_t s2;
    cudaStreamCreateWithFlags(&s2, cudaStreamNonBlocking);
    cudaEvent_t ev_fork, ev_join;
    cudaEventCreateWithFlags(&ev_fork, cudaEventDisableTiming);
    cudaEventCreateWithFlags(&ev_join, cudaEventDisableTiming);

    cudaEventRecord(ev_fork, 0);
    cudaStreamWaitEvent(s2, ev_fork, 0);

    // side stream: CSR build (zero -> count -> scan -> fill)
    zero_deg_kernel<<<(n + 255) / 256, 256, 0, s2>>>(n);
    count_deg_kernel<<<eb8, 256, 0, s2>>>(dst, E);
    scan_fused_kernel<<<nb, SCAN_B, 0, s2>>>(n, E);
    fill_edges_kernel<<<eb8, 256, 0, s2>>>(src, dst, E);

    // main stream: layer-1 projection, concurrent with CSR build
    gemm128_kernel<IN_CH><<<gemm_blocks, 128>>>(x, W1, P, n);

    cudaEventRecord(ev_join, s2);
    cudaStreamWaitEvent(0, ev_join, 0);

    // layer 1 aggregate (+b1, relu), layer 2 project + aggregate (+b2)
    spmm64_kernel<true><<<spmm_blocks, 256>>>(P, b1, H, n);
    gemm128_kernel<HID><<<gemm_blocks, 128>>>(H, W2, P, n);
    spmm64_kernel<false><<<spmm_blocks, 256>>>(P, b2, out, n);
}